// round 14
// baseline (speedup 1.0000x reference)
#include <cuda_runtime.h>
#include <cuda_fp16.h>
#include <math.h>
#include <stdint.h>

// Problem constants
#define NTOK   8192
#define DIM    1024
#define ODIM   1024
#define NEXP   8
#define TOPK   2
#define ASSIGN (NTOK*TOPK)

// GEMM tiling
#define BM 128
#define BN 256
#define BK 64
#define NSTAGE (DIM/BK)                 // 16
#define MAX_TILES (ASSIGN/BM + NEXP)    // 136
#define GEMM_THREADS 512                // 16 warps: 2 (m) x 8 (n), warp tile 64x32

// ---- GEMM smem layout (bytes), 3-stage pipeline, 1 CTA/SM ----
#define A_STRIDE_B 144
#define A_BUF      (128*A_STRIDE_B)     // 18432
#define A_OFF      0
#define B_STRIDE_B 528                  // 256 fp16 = 512B pad to 528B
#define B_BUF      (64*B_STRIDE_B)      // 33792
#define B_OFF      (3*A_BUF)            // 55296
#define TOK_OFF    (B_OFF + 3*B_BUF)    // 156672
#define GATE_OFF   (TOK_OFF + 512)
#define BE_OFF     (GATE_OFF + 512)
#define SMEM_TOTAL (BE_OFF + 1024)      // 158720

// gate/prep tiling
#define GT_TOK 16
#define GT_CD  128
#define GT_NCH (DIM/GT_CD)              // 8
#define GT_PAD 132
#define WS_PAD 1036
#define GATE_BLOCKS (NTOK/GT_TOK)       // 512
#define ZERO_BLOCKS 256
#define CONV_BLOCKS 256
#define TOTAL_BLOCKS (GATE_BLOCKS + ZERO_BLOCKS + CONV_BLOCKS)   // 1024

// ---------------- device scratch ----------------
__device__ int   g_counts[NEXP];        // zeroed by GEMM CTA(0,0) for next replay
__device__ int   g_done;
__device__ int   g_tile_expert[MAX_TILES];
__device__ int   g_tile_row[MAX_TILES];
__device__ int   g_tile_rows[MAX_TILES];
__device__ int   g_num_tiles;
__device__ int   g_btok [NEXP*NTOK];
__device__ float g_bgate[NEXP*NTOK];
__device__ __half g_xf[NTOK*DIM];
__device__ __half g_Wf[NEXP*DIM*ODIM];

// ---------------- PTX helpers ----------------
__device__ __forceinline__ uint32_t smem_u32(const void* p) {
    uint32_t a;
    asm("{ .reg .u64 t; cvta.to.shared.u64 t, %1; cvt.u32.u64 %0, t; }" : "=r"(a) : "l"(p));
    return a;
}
__device__ __forceinline__ void cp16(uint32_t dst, const void* src) {
    asm volatile("cp.async.cg.shared.global [%0], [%1], 16;" :: "r"(dst), "l"(src));
}
#define CP_COMMIT() asm volatile("cp.async.commit_group;" ::: "memory")
#define CP_WAIT(N)  asm volatile("cp.async.wait_group %0;" :: "n"(N) : "memory")

__device__ __forceinline__ void ldsm_x4(uint32_t* r, uint32_t addr) {
    asm volatile("ldmatrix.sync.aligned.m8n8.x4.shared.b16 {%0,%1,%2,%3}, [%4];"
        : "=r"(r[0]), "=r"(r[1]), "=r"(r[2]), "=r"(r[3]) : "r"(addr));
}
__device__ __forceinline__ void ldsm_x4_t(uint32_t* r, uint32_t addr) {
    asm volatile("ldmatrix.sync.aligned.m8n8.x4.trans.shared.b16 {%0,%1,%2,%3}, [%4];"
        : "=r"(r[0]), "=r"(r[1]), "=r"(r[2]), "=r"(r[3]) : "r"(addr));
}
__device__ __forceinline__ void mma_f16(float* c, const uint32_t* a, const uint32_t* b) {
    asm volatile(
        "mma.sync.aligned.m16n8k16.row.col.f32.f16.f16.f32 "
        "{%0,%1,%2,%3}, {%4,%5,%6,%7}, {%8,%9}, {%0,%1,%2,%3};"
        : "+f"(c[0]), "+f"(c[1]), "+f"(c[2]), "+f"(c[3])
        : "r"(a[0]), "r"(a[1]), "r"(a[2]), "r"(a[3]), "r"(b[0]), "r"(b[1]));
}

// ---------------- fused gate + convx + (out-zero / convw) heterogeneous blocks ----------------
__global__ void gateprep_kernel(const float* __restrict__ x,
                                const float* __restrict__ Wg,
                                const float* __restrict__ bg,
                                const float* __restrict__ We,
                                float* __restrict__ out, int out_elems)
{
    __shared__ float xs[2][GT_TOK][GT_PAD];
    __shared__ float ws[NEXP][WS_PAD];
    __shared__ int   s_last;

    int t = threadIdx.x;

    if (blockIdx.x >= GATE_BLOCKS) {
        int b = blockIdx.x - GATE_BLOCKS;
        if (b < ZERO_BLOCKS) {
            int i0 = b * 256 + t, str = ZERO_BLOCKS * 256;
            float4 z = make_float4(0.f, 0.f, 0.f, 0.f);
            for (int i = i0; i < out_elems / 4; i += str)
                reinterpret_cast<float4*>(out)[i] = z;
        } else {
            int i0 = (b - ZERO_BLOCKS) * 256 + t, str = CONV_BLOCKS * 256;
            __half2* o = reinterpret_cast<__half2*>(g_Wf);
            for (int i = i0; i < NEXP * DIM * ODIM / 4; i += str) {
                float4 v = reinterpret_cast<const float4*>(We)[i];
                o[i*2+0] = __floats2half2_rn(v.x, v.y);
                o[i*2+1] = __floats2half2_rn(v.z, v.w);
            }
        }
        return;
    }

    int n0  = blockIdx.x * GT_TOK;
    int tok = t >> 4;
    int sub = t & 15;
    int e   = sub & 7;
    int h   = sub >> 3;

    uint32_t xs_sm = smem_u32(&xs[0][0][0]);

    #pragma unroll
    for (int i = t; i < DIM * NEXP / 4; i += 256) {
        float4 v = reinterpret_cast<const float4*>(Wg)[i];
        int d = i >> 1, e0 = (i & 1) * 4;
        ws[e0+0][d] = v.x; ws[e0+1][d] = v.y;
        ws[e0+2][d] = v.z; ws[e0+3][d] = v.w;
    }
    #pragma unroll
    for (int i = t; i < 512; i += 256) {
        int tk = i >> 5, d4 = i & 31;
        cp16(xs_sm + (0 * GT_TOK + tk) * (GT_PAD * 4) + d4 * 16,
             x + (size_t)(n0 + tk) * DIM + d4 * 4);
    }
    CP_COMMIT();

    float acc = 0.f;

    #pragma unroll 1
    for (int c = 0; c < GT_NCH; c++) {
        int buf = c & 1;
        if (c + 1 < GT_NCH) {
            #pragma unroll
            for (int i = t; i < 512; i += 256) {
                int tk = i >> 5, d4 = i & 31;
                cp16(xs_sm + ((buf ^ 1) * GT_TOK + tk) * (GT_PAD * 4) + d4 * 16,
                     x + (size_t)(n0 + tk) * DIM + (c + 1) * GT_CD + d4 * 4);
            }
            CP_COMMIT();
            CP_WAIT(1);
        } else {
            CP_WAIT(0);
        }
        __syncthreads();
        #pragma unroll
        for (int i = t; i < 512; i += 256) {
            int tk = i >> 5, d4 = i & 31;
            float4 v = *reinterpret_cast<const float4*>(&xs[buf][tk][d4 * 4]);
            size_t goff = (size_t)(n0 + tk) * DIM + c * GT_CD + d4 * 4;
            __half2* o = reinterpret_cast<__half2*>(g_xf + goff);
            o[0] = __floats2half2_rn(v.x, v.y);
            o[1] = __floats2half2_rn(v.z, v.w);
        }
        const float* xp = &xs[buf][tok][h * 64];
        const float* wp = &ws[e][c * GT_CD + h * 64];
        #pragma unroll
        for (int d = 0; d < 64; d += 4) {
            float4 xv = *reinterpret_cast<const float4*>(xp + d);
            float4 wv = *reinterpret_cast<const float4*>(wp + d);
            acc += xv.x*wv.x + xv.y*wv.y + xv.z*wv.z + xv.w*wv.w;
        }
        __syncthreads();
    }
    float v = acc + __shfl_xor_sync(0xffffffffu, acc, 8) + bg[e];

    int idx = e;
    float bv = v;  int bi = idx;
    #pragma unroll
    for (int off = 4; off; off >>= 1) {
        float ov = __shfl_xor_sync(0xffffffffu, bv, off);
        int   oi = __shfl_xor_sync(0xffffffffu, bi, off);
        if (ov > bv || (ov == bv && oi < bi)) { bv = ov; bi = oi; }
    }
    float sv = (idx == bi) ? -INFINITY : v;
    int   si = idx;
    #pragma unroll
    for (int off = 4; off; off >>= 1) {
        float ov = __shfl_xor_sync(0xffffffffu, sv, off);
        int   oi = __shfl_xor_sync(0xffffffffu, si, off);
        if (ov > sv || (ov == sv && oi < si)) { sv = ov; si = oi; }
    }
    if (sub == 0) {
        int n = n0 + tok;
        float w1 = 1.0f / (1.0f + expf(sv - bv));
        float w2 = 1.0f - w1;
        int p1 = atomicAdd(&g_counts[bi], 1);
        g_btok [bi * NTOK + p1] = n;
        g_bgate[bi * NTOK + p1] = w1;
        int p2 = atomicAdd(&g_counts[si], 1);
        g_btok [si * NTOK + p2] = n;
        g_bgate[si * NTOK + p2] = w2;
    }

    __syncthreads();
    if (t == 0) {
        __threadfence();
        int d = atomicAdd(&g_done, 1);
        s_last = (d == GATE_BLOCKS - 1);
    }
    __syncthreads();
    if (s_last && t < 32) {
        int c  = (t < NEXP) ? g_counts[t] : 0;
        int nt = (c + BM - 1) / BM;
        int tpre = 0;
        #pragma unroll
        for (int i = 0; i < NEXP; i++) {
            int ti = __shfl_sync(0xffffffffu, nt, i);
            if (i < t) tpre += ti;
        }
        if (t < NEXP) {
            for (int r = 0, k = 0; r < c; r += BM, k++) {
                g_tile_expert[tpre + k] = t;
                g_tile_row[tpre + k]    = r;
                g_tile_rows[tpre + k]   = min(BM, c - r);
            }
        }
        int total = __shfl_sync(0xffffffffu, tpre + nt, NEXP - 1);
        if (t == 0) g_num_tiles = total;
    }
}

// ---------------- fp16 HMMA grouped GEMM: 512 threads, BN=256, 3-stage ----------------
__device__ __forceinline__ void load_stage(uint32_t sm, int k0, int buf,
                                           int e, int n0, const int* s_tok)
{
    int t = threadIdx.x;
    uint32_t abase = sm + A_OFF + buf * A_BUF;
    uint32_t bbase = sm + B_OFF + buf * B_BUF;
    // A: 128 rows x 64 fp16 = 1024 16B-chunks (8/row)
    #pragma unroll
    for (int c = t; c < 1024; c += GEMM_THREADS) {
        int r = c >> 3, c8 = c & 7;
        int tok = s_tok[r];
        size_t off = ((size_t)tok << 10) + k0 + (c8 << 3);
        cp16(abase + r * A_STRIDE_B + c8 * 16, g_xf + off);
    }
    // B: 64 rows (k) x 256 fp16 = 2048 chunks (32/row)
    #pragma unroll
    for (int c = t; c < 2048; c += GEMM_THREADS) {
        int kr = c >> 5, c32 = c & 31;
        size_t off = ((size_t)(e * DIM + k0 + kr) << 10) + n0 + (c32 << 3);
        cp16(bbase + kr * B_STRIDE_B + c32 * 16, g_Wf + off);
    }
    CP_COMMIT();
}

__global__ __launch_bounds__(GEMM_THREADS, 1)
void moe_gemm_kernel(const float* __restrict__ be, float* __restrict__ out)
{
    extern __shared__ char dsm[];
    uint32_t sm = smem_u32(dsm);
    int t    = threadIdx.x;
    int tile = blockIdx.x;

    // reset gate counters for the NEXT launch/replay (no reader in this kernel)
    if (tile == 0 && blockIdx.y == 0) {
        if (t < NEXP) g_counts[t] = 0;
        if (t == 0)   g_done = 0;
    }

    if (tile >= g_num_tiles) return;
    int e    = g_tile_expert[tile];
    int row0 = g_tile_row[tile];
    int rows = g_tile_rows[tile];
    int n0   = blockIdx.y * BN;
    int wid  = t >> 5, lane = t & 31;
    int wm   = wid & 1;          // warp m (2) -> 64 rows
    int wn   = wid >> 1;         // warp n (8) -> 32 cols

    int*   s_tok  = (int*)  (dsm + TOK_OFF);
    float* s_gate = (float*)(dsm + GATE_OFF);
    float* s_be   = (float*)(dsm + BE_OFF);

    if (t < BM) {
        if (t < rows) {
            s_tok [t] = g_btok [e * NTOK + row0 + t];
            s_gate[t] = g_bgate[e * NTOK + row0 + t];
        } else {
            s_tok [t] = 0;
            s_gate[t] = 0.f;
        }
    }
    if (t < BN) s_be[t] = be[e * ODIM + n0 + t];
    __syncthreads();

    float acc[4][4][4];
    #pragma unroll
    for (int i = 0; i < 4; i++)
        #pragma unroll
        for (int j = 0; j < 4; j++)
            #pragma unroll
            for (int q = 0; q < 4; q++) acc[i][j][q] = 0.f;

    load_stage(sm, 0,  0, e, n0, s_tok);
    load_stage(sm, BK, 1, e, n0, s_tok);

    #pragma unroll 1
    for (int s = 0; s < NSTAGE; s++) {
        int buf = s % 3;
        if (s == NSTAGE - 1) { CP_WAIT(0); } else { CP_WAIT(1); }
        __syncthreads();
        if (s + 2 < NSTAGE)
            load_stage(sm, (s + 2) * BK, (s + 2) % 3, e, n0, s_tok);

        uint32_t abase = sm + A_OFF + buf * A_BUF;
        uint32_t bbase = sm + B_OFF + buf * B_BUF;
        #pragma unroll
        for (int ks = 0; ks < 4; ks++) {
            uint32_t a[4][4], b[4][2];
            #pragma unroll
            for (int mi = 0; mi < 4; mi++) {
                int row = wm * 64 + mi * 16 + (lane & 15);
                ldsm_x4(a[mi], abase + row * A_STRIDE_B + ks * 32 + (lane >> 4) * 16);
            }
            #pragma unroll
            for (int np = 0; np < 2; np++) {
                int krow = ks * 16 + (lane & 15);
                int ncol = wn * 32 + np * 16 + (lane >> 4) * 8;
                uint32_t tb[4];
                ldsm_x4_t(tb, bbase + krow * B_STRIDE_B + ncol * 2);
                b[np*2][0]   = tb[0]; b[np*2][1]   = tb[1];
                b[np*2+1][0] = tb[2]; b[np*2+1][1] = tb[3];
            }
            #pragma unroll
            for (int mi = 0; mi < 4; mi++)
                #pragma unroll
                for (int ni = 0; ni < 4; ni++)
                    mma_f16(acc[mi][ni], a[mi], b[ni]);
        }
    }

    int r_in  = lane >> 2;
    int c_in  = (lane & 3) * 2;
    #pragma unroll
    for (int mi = 0; mi < 4; mi++) {
        int rbase = wm * 64 + mi * 16 + r_in;
        int tok0 = s_tok[rbase];     float g0 = s_gate[rbase];
        int tok1 = s_tok[rbase + 8]; float g1 = s_gate[rbase + 8];
        float* o0 = out + (size_t)tok0 * ODIM + n0;
        float* o1 = out + (size_t)tok1 * ODIM + n0;
        #pragma unroll
        for (int ni = 0; ni < 4; ni++) {
            int col = wn * 32 + ni * 8 + c_in;
            float b0 = s_be[col], b1 = s_be[col + 1];
            if (g0 != 0.f) {
                atomicAdd(o0 + col,     g0 * (acc[mi][ni][0] + b0));
                atomicAdd(o0 + col + 1, g0 * (acc[mi][ni][1] + b1));
            }
            if (g1 != 0.f) {
                atomicAdd(o1 + col,     g1 * (acc[mi][ni][2] + b0));
                atomicAdd(o1 + col + 1, g1 * (acc[mi][ni][3] + b1));
            }
        }
    }
}

// ---------------- launch: 2 kernels total ----------------
extern "C" void kernel_launch(void* const* d_in, const int* in_sizes, int n_in,
                              void* d_out, int out_size)
{
    const float* x  = (const float*)d_in[0];
    const float* We = (const float*)d_in[1];
    const float* be = (const float*)d_in[2];
    const float* Wg = (const float*)d_in[3];
    const float* bg = (const float*)d_in[4];
    float* out = (float*)d_out;

    static int smem_set = 0;
    if (!smem_set) {
        cudaFuncSetAttribute(moe_gemm_kernel,
                             cudaFuncAttributeMaxDynamicSharedMemorySize, SMEM_TOTAL);
        smem_set = 1;
    }

    gateprep_kernel<<<TOTAL_BLOCKS, 256>>>(x, Wg, bg, We, out, out_size);
    dim3 g(MAX_TILES, ODIM / BN);
    moe_gemm_kernel<<<g, GEMM_THREADS, SMEM_TOTAL>>>(be, out);
}

// round 15
// speedup vs baseline: 1.1978x; 1.1978x over previous
#include <cuda_runtime.h>
#include <cuda_fp16.h>
#include <math.h>
#include <stdint.h>

// Problem constants
#define NTOK   8192
#define DIM    1024
#define ODIM   1024
#define NEXP   8
#define TOPK   2
#define ASSIGN (NTOK*TOPK)

// GEMM tiling (validated R13 config: 2 CTAs/SM)
#define BM 128
#define BN 128
#define BK 64
#define NSTAGE (DIM/BK)                 // 16
#define MAX_TILES (ASSIGN/BM + NEXP)    // 136
#define GEMM_THREADS 256                // 8 warps: 2 (m) x 4 (n), warp tile 64x32

// ---- GEMM smem layout (bytes), 3-stage pipeline, 2 CTAs/SM ----
#define A_STRIDE_B 144
#define A_BUF      (128*A_STRIDE_B)     // 18432
#define A_OFF      0
#define B_STRIDE_B 272
#define B_BUF      (64*B_STRIDE_B)      // 17408
#define B_OFF      (3*A_BUF)            // 55296
#define TOK_OFF    (B_OFF + 3*B_BUF)    // 107520
#define GATE_OFF   (TOK_OFF + 512)
#define BE_OFF     (GATE_OFF + 512)
#define SMEM_TOTAL (BE_OFF + 512)       // 108544

// gate/prep tiling
#define GT_TOK 16
#define GT_CD  128
#define GT_NCH (DIM/GT_CD)              // 8
#define GT_PAD 132
#define WS_PAD 1036
#define GATE_BLOCKS (NTOK/GT_TOK)       // 512
#define ZERO_BLOCKS 256
#define CONV_BLOCKS 256
#define TOTAL_BLOCKS (GATE_BLOCKS + ZERO_BLOCKS + CONV_BLOCKS)   // 1024

// ---------------- device scratch ----------------
__device__ int   g_counts[NEXP];        // zeroed by GEMM CTA(0,0) for next replay
__device__ int   g_done;
__device__ int   g_tile_expert[MAX_TILES];
__device__ int   g_tile_row[MAX_TILES];
__device__ int   g_tile_rows[MAX_TILES];
__device__ int   g_num_tiles;
__device__ int   g_btok [NEXP*NTOK];
__device__ float g_bgate[NEXP*NTOK];
__device__ __half g_xf[NTOK*DIM];
__device__ __half g_Wf[NEXP*DIM*ODIM];

// ---------------- PTX helpers ----------------
__device__ __forceinline__ uint32_t smem_u32(const void* p) {
    uint32_t a;
    asm("{ .reg .u64 t; cvta.to.shared.u64 t, %1; cvt.u32.u64 %0, t; }" : "=r"(a) : "l"(p));
    return a;
}
__device__ __forceinline__ void cp16(uint32_t dst, const void* src) {
    asm volatile("cp.async.cg.shared.global [%0], [%1], 16;" :: "r"(dst), "l"(src));
}
#define CP_COMMIT() asm volatile("cp.async.commit_group;" ::: "memory")
#define CP_WAIT(N)  asm volatile("cp.async.wait_group %0;" :: "n"(N) : "memory")

__device__ __forceinline__ void ldsm_x4(uint32_t* r, uint32_t addr) {
    asm volatile("ldmatrix.sync.aligned.m8n8.x4.shared.b16 {%0,%1,%2,%3}, [%4];"
        : "=r"(r[0]), "=r"(r[1]), "=r"(r[2]), "=r"(r[3]) : "r"(addr));
}
__device__ __forceinline__ void ldsm_x4_t(uint32_t* r, uint32_t addr) {
    asm volatile("ldmatrix.sync.aligned.m8n8.x4.trans.shared.b16 {%0,%1,%2,%3}, [%4];"
        : "=r"(r[0]), "=r"(r[1]), "=r"(r[2]), "=r"(r[3]) : "r"(addr));
}
__device__ __forceinline__ void mma_f16(float* c, const uint32_t* a, const uint32_t* b) {
    asm volatile(
        "mma.sync.aligned.m16n8k16.row.col.f32.f16.f16.f32 "
        "{%0,%1,%2,%3}, {%4,%5,%6,%7}, {%8,%9}, {%0,%1,%2,%3};"
        : "+f"(c[0]), "+f"(c[1]), "+f"(c[2]), "+f"(c[3])
        : "r"(a[0]), "r"(a[1]), "r"(a[2]), "r"(a[3]), "r"(b[0]), "r"(b[1]));
}

// ---------------- fused gate + convx + (out-zero / convw) heterogeneous blocks ----------------
__global__ void gateprep_kernel(const float* __restrict__ x,
                                const float* __restrict__ Wg,
                                const float* __restrict__ bg,
                                const float* __restrict__ We,
                                float* __restrict__ out, int out_elems)
{
    __shared__ float xs[2][GT_TOK][GT_PAD];
    __shared__ float ws[NEXP][WS_PAD];
    __shared__ int   s_last;

    int t = threadIdx.x;

    if (blockIdx.x >= GATE_BLOCKS) {
        int b = blockIdx.x - GATE_BLOCKS;
        if (b < ZERO_BLOCKS) {
            int i0 = b * 256 + t, str = ZERO_BLOCKS * 256;
            float4 z = make_float4(0.f, 0.f, 0.f, 0.f);
            for (int i = i0; i < out_elems / 4; i += str)
                reinterpret_cast<float4*>(out)[i] = z;
        } else {
            int i0 = (b - ZERO_BLOCKS) * 256 + t, str = CONV_BLOCKS * 256;
            __half2* o = reinterpret_cast<__half2*>(g_Wf);
            for (int i = i0; i < NEXP * DIM * ODIM / 4; i += str) {
                float4 v = reinterpret_cast<const float4*>(We)[i];
                o[i*2+0] = __floats2half2_rn(v.x, v.y);
                o[i*2+1] = __floats2half2_rn(v.z, v.w);
            }
        }
        return;
    }

    int n0  = blockIdx.x * GT_TOK;
    int tok = t >> 4;
    int sub = t & 15;
    int e   = sub & 7;
    int h   = sub >> 3;

    uint32_t xs_sm = smem_u32(&xs[0][0][0]);

    #pragma unroll
    for (int i = t; i < DIM * NEXP / 4; i += 256) {
        float4 v = reinterpret_cast<const float4*>(Wg)[i];
        int d = i >> 1, e0 = (i & 1) * 4;
        ws[e0+0][d] = v.x; ws[e0+1][d] = v.y;
        ws[e0+2][d] = v.z; ws[e0+3][d] = v.w;
    }
    #pragma unroll
    for (int i = t; i < 512; i += 256) {
        int tk = i >> 5, d4 = i & 31;
        cp16(xs_sm + (0 * GT_TOK + tk) * (GT_PAD * 4) + d4 * 16,
             x + (size_t)(n0 + tk) * DIM + d4 * 4);
    }
    CP_COMMIT();

    float acc = 0.f;

    #pragma unroll 1
    for (int c = 0; c < GT_NCH; c++) {
        int buf = c & 1;
        if (c + 1 < GT_NCH) {
            #pragma unroll
            for (int i = t; i < 512; i += 256) {
                int tk = i >> 5, d4 = i & 31;
                cp16(xs_sm + ((buf ^ 1) * GT_TOK + tk) * (GT_PAD * 4) + d4 * 16,
                     x + (size_t)(n0 + tk) * DIM + (c + 1) * GT_CD + d4 * 4);
            }
            CP_COMMIT();
            CP_WAIT(1);
        } else {
            CP_WAIT(0);
        }
        __syncthreads();
        #pragma unroll
        for (int i = t; i < 512; i += 256) {
            int tk = i >> 5, d4 = i & 31;
            float4 v = *reinterpret_cast<const float4*>(&xs[buf][tk][d4 * 4]);
            size_t goff = (size_t)(n0 + tk) * DIM + c * GT_CD + d4 * 4;
            __half2* o = reinterpret_cast<__half2*>(g_xf + goff);
            o[0] = __floats2half2_rn(v.x, v.y);
            o[1] = __floats2half2_rn(v.z, v.w);
        }
        const float* xp = &xs[buf][tok][h * 64];
        const float* wp = &ws[e][c * GT_CD + h * 64];
        #pragma unroll
        for (int d = 0; d < 64; d += 4) {
            float4 xv = *reinterpret_cast<const float4*>(xp + d);
            float4 wv = *reinterpret_cast<const float4*>(wp + d);
            acc += xv.x*wv.x + xv.y*wv.y + xv.z*wv.z + xv.w*wv.w;
        }
        __syncthreads();
    }
    float v = acc + __shfl_xor_sync(0xffffffffu, acc, 8) + bg[e];

    int idx = e;
    float bv = v;  int bi = idx;
    #pragma unroll
    for (int off = 4; off; off >>= 1) {
        float ov = __shfl_xor_sync(0xffffffffu, bv, off);
        int   oi = __shfl_xor_sync(0xffffffffu, bi, off);
        if (ov > bv || (ov == bv && oi < bi)) { bv = ov; bi = oi; }
    }
    float sv = (idx == bi) ? -INFINITY : v;
    int   si = idx;
    #pragma unroll
    for (int off = 4; off; off >>= 1) {
        float ov = __shfl_xor_sync(0xffffffffu, sv, off);
        int   oi = __shfl_xor_sync(0xffffffffu, si, off);
        if (ov > sv || (ov == sv && oi < si)) { sv = ov; si = oi; }
    }
    if (sub == 0) {
        int n = n0 + tok;
        float w1 = 1.0f / (1.0f + expf(sv - bv));
        float w2 = 1.0f - w1;
        int p1 = atomicAdd(&g_counts[bi], 1);
        g_btok [bi * NTOK + p1] = n;
        g_bgate[bi * NTOK + p1] = w1;
        int p2 = atomicAdd(&g_counts[si], 1);
        g_btok [si * NTOK + p2] = n;
        g_bgate[si * NTOK + p2] = w2;
    }

    __syncthreads();
    if (t == 0) {
        __threadfence();
        int d = atomicAdd(&g_done, 1);
        s_last = (d == GATE_BLOCKS - 1);
    }
    __syncthreads();
    if (s_last && t < 32) {
        int c  = (t < NEXP) ? g_counts[t] : 0;
        int nt = (c + BM - 1) / BM;
        int tpre = 0;
        #pragma unroll
        for (int i = 0; i < NEXP; i++) {
            int ti = __shfl_sync(0xffffffffu, nt, i);
            if (i < t) tpre += ti;
        }
        if (t < NEXP) {
            for (int r = 0, k = 0; r < c; r += BM, k++) {
                g_tile_expert[tpre + k] = t;
                g_tile_row[tpre + k]    = r;
                g_tile_rows[tpre + k]   = min(BM, c - r);
            }
        }
        int total = __shfl_sync(0xffffffffu, tpre + nt, NEXP - 1);
        if (t == 0) g_num_tiles = total;
    }
}

// ---------------- fp16 HMMA grouped GEMM (R13 config + B-first prologue) ----------------
__device__ __forceinline__ void load_A(uint32_t sm, int k0, int buf, const int* s_tok)
{
    int t = threadIdx.x;
    uint32_t abase = sm + A_OFF + buf * A_BUF;
    #pragma unroll
    for (int c = t; c < 1024; c += GEMM_THREADS) {
        int r = c >> 3, c8 = c & 7;
        int tok = s_tok[r];
        size_t off = ((size_t)tok << 10) + k0 + (c8 << 3);
        cp16(abase + r * A_STRIDE_B + c8 * 16, g_xf + off);
    }
}
__device__ __forceinline__ void load_B(uint32_t sm, int k0, int buf, int e, int n0)
{
    int t = threadIdx.x;
    uint32_t bbase = sm + B_OFF + buf * B_BUF;
    #pragma unroll
    for (int c = t; c < 1024; c += GEMM_THREADS) {
        int kr = c >> 4, c16 = c & 15;
        size_t off = ((size_t)(e * DIM + k0 + kr) << 10) + n0 + (c16 << 3);
        cp16(bbase + kr * B_STRIDE_B + c16 * 16, g_Wf + off);
    }
}

__global__ __launch_bounds__(GEMM_THREADS, 2)
void moe_gemm_kernel(const float* __restrict__ be, float* __restrict__ out)
{
    extern __shared__ char dsm[];
    uint32_t sm = smem_u32(dsm);
    int t    = threadIdx.x;
    int tile = blockIdx.x;

    // reset gate counters for the NEXT launch/replay (no reader in this kernel)
    if (tile == 0 && blockIdx.y == 0) {
        if (t < NEXP) g_counts[t] = 0;
        if (t == 0)   g_done = 0;
    }

    if (tile >= g_num_tiles) return;
    int e    = g_tile_expert[tile];
    int row0 = g_tile_row[tile];
    int rows = g_tile_rows[tile];
    int n0   = blockIdx.y * BN;
    int wid  = t >> 5, lane = t & 31;
    int wm   = wid & 1;
    int wn   = wid >> 1;

    int*   s_tok  = (int*)  (dsm + TOK_OFF);
    float* s_gate = (float*)(dsm + GATE_OFF);
    float* s_be   = (float*)(dsm + BE_OFF);

    // B tiles for stages 0/1 are token-independent: start them NOW
    load_B(sm, 0,  0, e, n0); CP_COMMIT();     // group: B0
    load_B(sm, BK, 1, e, n0); CP_COMMIT();     // group: B1

    if (t < BM) {
        if (t < rows) {
            s_tok [t] = g_btok [e * NTOK + row0 + t];
            s_gate[t] = g_bgate[e * NTOK + row0 + t];
        } else {
            s_tok [t] = 0;
            s_gate[t] = 0.f;
        }
    }
    if (t < BN) s_be[t] = be[e * ODIM + n0 + t];
    __syncthreads();

    load_A(sm, 0,  0, s_tok); CP_COMMIT();     // group: A0
    load_A(sm, BK, 1, s_tok); CP_COMMIT();     // group: A1

    float acc[4][4][4];
    #pragma unroll
    for (int i = 0; i < 4; i++)
        #pragma unroll
        for (int j = 0; j < 4; j++)
            #pragma unroll
            for (int q = 0; q < 4; q++) acc[i][j][q] = 0.f;

    #pragma unroll 1
    for (int s = 0; s < NSTAGE; s++) {
        int buf = s % 3;
        if (s == NSTAGE - 1) { CP_WAIT(0); } else { CP_WAIT(1); }
        __syncthreads();
        if (s + 2 < NSTAGE) {
            load_A(sm, (s + 2) * BK, (s + 2) % 3, s_tok);
            load_B(sm, (s + 2) * BK, (s + 2) % 3, e, n0);
            CP_COMMIT();
        }

        uint32_t abase = sm + A_OFF + buf * A_BUF;
        uint32_t bbase = sm + B_OFF + buf * B_BUF;
        #pragma unroll
        for (int ks = 0; ks < 4; ks++) {
            uint32_t a[4][4], b[4][2];
            #pragma unroll
            for (int mi = 0; mi < 4; mi++) {
                int row = wm * 64 + mi * 16 + (lane & 15);
                ldsm_x4(a[mi], abase + row * A_STRIDE_B + ks * 32 + (lane >> 4) * 16);
            }
            #pragma unroll
            for (int np = 0; np < 2; np++) {
                int krow = ks * 16 + (lane & 15);
                int ncol = wn * 32 + np * 16 + (lane >> 4) * 8;
                uint32_t tb[4];
                ldsm_x4_t(tb, bbase + krow * B_STRIDE_B + ncol * 2);
                b[np*2][0]   = tb[0]; b[np*2][1]   = tb[1];
                b[np*2+1][0] = tb[2]; b[np*2+1][1] = tb[3];
            }
            #pragma unroll
            for (int mi = 0; mi < 4; mi++)
                #pragma unroll
                for (int ni = 0; ni < 4; ni++)
                    mma_f16(acc[mi][ni], a[mi], b[ni]);
        }
    }

    int r_in  = lane >> 2;
    int c_in  = (lane & 3) * 2;
    #pragma unroll
    for (int mi = 0; mi < 4; mi++) {
        int rbase = wm * 64 + mi * 16 + r_in;
        int tok0 = s_tok[rbase];     float g0 = s_gate[rbase];
        int tok1 = s_tok[rbase + 8]; float g1 = s_gate[rbase + 8];
        float* o0 = out + (size_t)tok0 * ODIM + n0;
        float* o1 = out + (size_t)tok1 * ODIM + n0;
        #pragma unroll
        for (int ni = 0; ni < 4; ni++) {
            int col = wn * 32 + ni * 8 + c_in;
            float b0 = s_be[col], b1 = s_be[col + 1];
            if (g0 != 0.f) {
                atomicAdd(o0 + col,     g0 * (acc[mi][ni][0] + b0));
                atomicAdd(o0 + col + 1, g0 * (acc[mi][ni][1] + b1));
            }
            if (g1 != 0.f) {
                atomicAdd(o1 + col,     g1 * (acc[mi][ni][2] + b0));
                atomicAdd(o1 + col + 1, g1 * (acc[mi][ni][3] + b1));
            }
        }
    }
}

// ---------------- launch: 2 kernels total ----------------
extern "C" void kernel_launch(void* const* d_in, const int* in_sizes, int n_in,
                              void* d_out, int out_size)
{
    const float* x  = (const float*)d_in[0];
    const float* We = (const float*)d_in[1];
    const float* be = (const float*)d_in[2];
    const float* Wg = (const float*)d_in[3];
    const float* bg = (const float*)d_in[4];
    float* out = (float*)d_out;

    static int smem_set = 0;
    if (!smem_set) {
        cudaFuncSetAttribute(moe_gemm_kernel,
                             cudaFuncAttributeMaxDynamicSharedMemorySize, SMEM_TOTAL);
        smem_set = 1;
    }

    gateprep_kernel<<<TOTAL_BLOCKS, 256>>>(x, Wg, bg, We, out, out_size);
    dim3 g(MAX_TILES, ODIM / BN);
    moe_gemm_kernel<<<g, GEMM_THREADS, SMEM_TOTAL>>>(be, out);
}